// round 8
// baseline (speedup 1.0000x reference)
#include <cuda_runtime.h>
#include <cuda_bf16.h>
#include <math.h>
#include <stdint.h>

// ---------------------------------------------------------------------------
// Problem constants
// ---------------------------------------------------------------------------
#define NTOK 8192           // 8 * 32 * 32 tokens at stride 32
#define C    768            // channels
#define K2C  384            // C/2 (k-pair rows of packed weights)
#define NE   4              // experts

#define S4_ELEMS  50331648  // 8*96*256*256
#define S8_ELEMS  25165824  // 8*192*128*128
#define S16_ELEMS 12582912  // 8*384*64*64
#define OFF_S8   50331648
#define OFF_S16  75497472
#define OFF_S32  88080384

// GEMM tiling (bf16 m16n8k16, block 128x128, 4 warps of 64x64)
#define TBM 128
#define TBN 128
#define TBK 32              // k per smem stage (2 x k16 mma steps)
#define AS_W 20             // u32 words per A smem row (32 bf16 data + pad)
#define BS_W 136            // u32 words per B smem row (128 data + 8 pad)
#define A_STAGE_W (TBM * AS_W)        // 2560 words
#define B_STAGE_W ((TBK/2) * BS_W)    // 2176 words
#define SMEM_PLAIN_BYTES ((2*A_STAGE_W + 2*B_STAGE_W) * 4)          // 37888
#define SMEM_SPLIT_BYTES ((4*A_STAGE_W + 4*B_STAGE_W) * 4)          // 75776

#define MT (NTOK / TBM)     // 64 m-tiles
#define NT (C / TBN)        // 6  n-tiles
#define NB_COPY 148         // copy blocks PREPENDED per GEMM launch
#define NB_CONV 256         // expert-weight convert blocks (gate launch only)

// ---------------------------------------------------------------------------
// Scratch (device globals: no allocation allowed)
// ---------------------------------------------------------------------------
__device__ __nv_bfloat16 g_Xb[NTOK * C];   // tokens hi bf16
__device__ __nv_bfloat16 g_Xl[NTOK * C];   // tokens lo bf16 (split residual)
__device__ __nv_bfloat16 g_H [NTOK * C];   // expert hidden (compact, bf16)
__device__ float g_X [NTOK * C];           // Y (expert output, fp32, compact)
__device__ float4 g_lpart[NT * NTOK];      // per-n-block partial logits
__device__ uint32_t g_gw1h[K2C * C];       // gate w1 hi, k-pair packed bf16x2
__device__ uint32_t g_gw1l[K2C * C];       // gate w1 lo
__device__ uint32_t g_ew1b[NE * K2C * C];  // expert w1 bf16 packed
__device__ uint32_t g_ew2b[NE * K2C * C];  // expert w2 bf16 packed
__device__ int   g_top[NTOK];
__device__ float g_gv[NTOK];
__device__ int   g_perm[NTOK];
__device__ int   g_tok2g[NTOK];
__device__ int   g_offsets[NE + 1];

// ---------------------------------------------------------------------------
// Helpers
// ---------------------------------------------------------------------------
__device__ __forceinline__ float gelu_tanh(float x) {
    float x3 = x * x * x;
    return 0.5f * x * (1.0f + tanhf(0.7978845608028654f * x + 0.035677408136300125f * x3));
}

__device__ __forceinline__ void cp_async16(uint32_t smem_dst, const void* gsrc, bool valid) {
    int sz = valid ? 16 : 0;
    asm volatile("cp.async.cg.shared.global [%0], [%1], 16, %2;\n"
                 :: "r"(smem_dst), "l"(gsrc), "r"(sz));
}
__device__ __forceinline__ void cp_commit() { asm volatile("cp.async.commit_group;\n"); }
__device__ __forceinline__ void cp_wait0()  { asm volatile("cp.async.wait_group 0;\n"); }

__device__ __forceinline__ void mma_bf16(float* c, const uint32_t* a, const uint32_t* b) {
    asm volatile(
        "mma.sync.aligned.m16n8k16.row.col.f32.bf16.bf16.f32 "
        "{%0,%1,%2,%3},{%4,%5,%6,%7},{%8,%9},{%0,%1,%2,%3};\n"
        : "+f"(c[0]), "+f"(c[1]), "+f"(c[2]), "+f"(c[3])
        : "r"(a[0]), "r"(a[1]), "r"(a[2]), "r"(a[3]), "r"(b[0]), "r"(b[1]));
}

__device__ __forceinline__ uint32_t pack_bf16x2(float v0, float v1) {
    uint32_t r;
    asm("cvt.rn.bf16x2.f32 %0, %1, %2;" : "=r"(r) : "f"(v1), "f"(v0));
    return r;
}

// grid-stride copy, 8 float4 / thread / window (cnt4 % 1024 == 0)
__device__ __forceinline__ void do_copy(int blk, int tid,
                                        const float4* __restrict__ s,
                                        float4* __restrict__ d, int cnt4) {
    size_t i = (size_t)blk * 1024 + tid;
    const size_t stride = (size_t)NB_COPY * 1024;
    for (; i < (size_t)cnt4; i += stride) {
        float4 v0 = s[i];
        float4 v1 = s[i + 128];
        float4 v2 = s[i + 256];
        float4 v3 = s[i + 384];
        float4 v4 = s[i + 512];
        float4 v5 = s[i + 640];
        float4 v6 = s[i + 768];
        float4 v7 = s[i + 896];
        d[i]       = v0; d[i + 128] = v1; d[i + 256] = v2; d[i + 384] = v3;
        d[i + 512] = v4; d[i + 640] = v5; d[i + 768] = v6; d[i + 896] = v7;
    }
}

// ---------------------------------------------------------------------------
// 1. prep launch: BCHW->token transpose (hi/lo bf16) + gate-w1 split/pack
// ---------------------------------------------------------------------------
__global__ void prep_k(const float* __restrict__ s32, const float* __restrict__ gw1) {
    int blk = blockIdx.x;
    int tx = threadIdx.x, ty = threadIdx.y;   // (32, 8)

    if (blk < 6144) {
        __shared__ float tile[32][33];
        int bx = blk & 31;
        int t  = blk >> 5;
        int by = t % 24;
        int bz = t / 24;
        int c0 = by * 32, hw0 = bx * 32;
        const float* src = s32 + ((size_t)bz * C + c0) * 1024 + hw0;
        #pragma unroll
        for (int j = 0; j < 32; j += 8)
            tile[ty + j][tx] = src[(ty + j) * 1024 + tx];
        __syncthreads();
        size_t dbase = ((size_t)(bz * 1024 + hw0)) * C + c0;
        #pragma unroll
        for (int j = 0; j < 32; j += 8) {
            float x = tile[tx][ty + j];
            __nv_bfloat16 h = __float2bfloat16(x);
            float r = x - __bfloat162float(h);
            size_t idx = dbase + (size_t)(ty + j) * C + tx;
            g_Xb[idx] = h;
            g_Xl[idx] = __float2bfloat16(r);
        }
    } else {
        int tid = ty * 32 + tx;
        const int total = K2C * C;
        for (int w = (blk - 6144) * 256 + tid; w < total; w += 256 * 256) {
            int k2 = w / C, n = w - k2 * C;
            float w0 = gw1[(size_t)(2 * k2) * C + n];
            float w1 = gw1[(size_t)(2 * k2 + 1) * C + n];
            float h0 = __bfloat162float(__float2bfloat16(w0));
            float h1 = __bfloat162float(__float2bfloat16(w1));
            g_gw1h[w] = pack_bf16x2(h0, h1);
            g_gw1l[w] = pack_bf16x2(w0 - h0, w1 - h1);
        }
    }
}

// ---------------------------------------------------------------------------
// bf16 GEMM: block 128x128, 4 warps (2m x 2n) of 64x64, 128 threads.
//   MODE 0 (split-bf16): hidden = gelu(X@gw1+b1); epilogue reduces partial
//                        logits (hidden @ gw2) into g_lpart. No hidden store.
//   MODE 1 (plain bf16): H = gelu(gather(Xb)@ew1+b1) -> g_H (bf16)
//   MODE 2 (plain bf16): Y = (H@ew2+b2)*gate_val     -> g_X (fp32)
// Copy blocks first; MODE 0 also hosts expert-weight convert blocks.
// ---------------------------------------------------------------------------
template <int MODE>
__launch_bounds__(128, 2)
__global__ void mma_gemm_k(const float* __restrict__ Ball,
                           const float* __restrict__ gw2,
                           const float4* __restrict__ csrc, float4* __restrict__ cdst, int cnt4,
                           const float* __restrict__ cvt1, const float* __restrict__ cvt2,
                           int nbPre) {
    constexpr bool SPLIT = (MODE == 0);
    const int blk = blockIdx.x;
    const int tid = threadIdx.x;

    // ---- copy role -------------------------------------------------------
    if (blk < NB_COPY) { do_copy(blk, tid, csrc, cdst, cnt4); return; }

    // ---- expert weight convert role (gate launch only) -------------------
    if (MODE == 0 && blk < nbPre) {
        const int cb = blk - NB_COPY;
        const int WCNT = NE * K2C * C;
        for (int w = cb * 128 + tid; w < 2 * WCNT; w += NB_CONV * 128) {
            int wi = w;
            const float* src; uint32_t* dst;
            if (wi < WCNT) { src = cvt1; dst = g_ew1b; }
            else           { wi -= WCNT; src = cvt2; dst = g_ew2b; }
            int k2g = wi / C, n = wi - k2g * C;
            float w0 = src[(size_t)(2 * k2g) * C + n];
            float w1 = src[(size_t)(2 * k2g + 1) * C + n];
            dst[wi] = pack_bf16x2(w0, w1);
        }
        return;
    }

    // ---- GEMM role -------------------------------------------------------
    const int gblk = blk - nbPre;
    int e, bx, by;
    if (MODE == 0) { e = 0; bx = gblk & (MT - 1); by = gblk >> 6; }
    else { e = gblk / (MT * NT); int r = gblk - e * (MT * NT); bx = r & (MT - 1); by = r >> 6; }

    int base, cnt;
    if (MODE == 0) { base = 0; cnt = NTOK; }
    else           { base = g_offsets[e]; cnt = g_offsets[e + 1] - base; }

    const int m0 = bx * TBM;
    if (m0 >= cnt) return;
    const int n0 = by * TBN;

    const uint32_t* Wh = (MODE == 0) ? g_gw1h
                        : (MODE == 1) ? (g_ew1b + (size_t)e * K2C * C)
                                      : (g_ew2b + (size_t)e * K2C * C);
    const uint32_t* Wl = g_gw1l;   // only used when SPLIT
    const float* bias  = Ball + ((MODE == 0) ? 0 : e * C);

    extern __shared__ uint32_t sm[];
    uint32_t* AhB = sm;
    uint32_t* AlB = sm + 2 * A_STAGE_W;
    uint32_t* BhB = sm + (SPLIT ? 4 : 2) * A_STAGE_W;
    uint32_t* BlB = BhB + 2 * B_STAGE_W;
    const uint32_t sAh = (uint32_t)__cvta_generic_to_shared(AhB);
    const uint32_t sAl = (uint32_t)__cvta_generic_to_shared(AlB);
    const uint32_t sBh = (uint32_t)__cvta_generic_to_shared(BhB);
    const uint32_t sBl = (uint32_t)__cvta_generic_to_shared(BlB);

    const int wid  = tid >> 5;
    const int lane = tid & 31;
    const int g    = lane >> 2;
    const int tig  = lane & 3;
    const int mW   = (wid & 1) * 64;     // warps (0,2): m 0-63 ; (1,3): m 64-127
    const int nW   = (wid >> 1) * 64;    // warps (0,1): n 0-63 ; (2,3): n 64-127

    // A loader: 4 x 16B chunks / thread / stage (per array)
    const __nv_bfloat16* Asrc = (MODE == 2) ? g_H : g_Xb;
    const uint8_t* srcA[4]; const uint8_t* srcAL[4]; uint32_t dstA[4]; bool vA[4];
    #pragma unroll
    for (int i = 0; i < 4; i++) {
        int q = tid + i * 128;
        int chunk = q >> 7;          // 0..3
        int row   = q & 127;
        int m = m0 + row;
        bool v = (m < cnt);
        int ar = 0;
        if (v) {
            if      (MODE == 1) ar = g_perm[base + m];
            else if (MODE == 2) ar = base + m;
            else                ar = m;
        }
        size_t boff = (size_t)ar * C * 2 + chunk * 16;
        srcA[i]  = (const uint8_t*)Asrc + boff;
        srcAL[i] = (const uint8_t*)g_Xl + boff;
        dstA[i]  = (uint32_t)(row * AS_W + chunk * 4) * 4u;
        vA[i] = v;
    }
    // B loader: 4 x 16B chunks / thread / stage
    size_t srcBoff[4]; uint32_t dstB[4];
    #pragma unroll
    for (int i = 0; i < 4; i++) {
        int q = tid + i * 128;
        int k2r = q >> 5;            // 0..15
        int c   = q & 31;            // 0..31
        srcBoff[i] = (size_t)k2r * C + n0 + c * 4;
        dstB[i]    = (uint32_t)(k2r * BS_W + c * 4) * 4u;
    }

    float acc[4][8][4];
    #pragma unroll
    for (int mt = 0; mt < 4; mt++)
        #pragma unroll
        for (int nt = 0; nt < 8; nt++)
            #pragma unroll
            for (int r = 0; r < 4; r++) acc[mt][nt][r] = 0.f;

    const int T = C / TBK;  // 24

    // prologue: stage 0
    #pragma unroll
    for (int i = 0; i < 4; i++) cp_async16(sAh + dstA[i], srcA[i], vA[i]);
    if (SPLIT)
        #pragma unroll
        for (int i = 0; i < 4; i++) cp_async16(sAl + dstA[i], srcAL[i], vA[i]);
    #pragma unroll
    for (int i = 0; i < 4; i++) cp_async16(sBh + dstB[i], Wh + srcBoff[i], true);
    if (SPLIT)
        #pragma unroll
        for (int i = 0; i < 4; i++) cp_async16(sBl + dstB[i], Wl + srcBoff[i], true);
    cp_commit();

    for (int t = 0; t < T; t++) {
        const int cur = t & 1;
        cp_wait0();
        __syncthreads();

        if (t + 1 < T) {
            const int nxt = cur ^ 1;
            const int kb = (t + 1) * (TBK * 2);                 // bytes into A rows
            const size_t kw = (size_t)(t + 1) * (TBK / 2) * C;  // words into W
            #pragma unroll
            for (int i = 0; i < 4; i++)
                cp_async16(sAh + nxt * (A_STAGE_W * 4) + dstA[i], srcA[i] + kb, vA[i]);
            if (SPLIT)
                #pragma unroll
                for (int i = 0; i < 4; i++)
                    cp_async16(sAl + nxt * (A_STAGE_W * 4) + dstA[i], srcAL[i] + kb, vA[i]);
            #pragma unroll
            for (int i = 0; i < 4; i++)
                cp_async16(sBh + nxt * (B_STAGE_W * 4) + dstB[i], Wh + srcBoff[i] + kw, true);
            if (SPLIT)
                #pragma unroll
                for (int i = 0; i < 4; i++)
                    cp_async16(sBl + nxt * (B_STAGE_W * 4) + dstB[i], Wl + srcBoff[i] + kw, true);
            cp_commit();
        }

        const uint32_t* Ahc = AhB + cur * A_STAGE_W;
        const uint32_t* Alc = AlB + cur * A_STAGE_W;
        const uint32_t* Bhc = BhB + cur * B_STAGE_W;
        const uint32_t* Blc = BlB + cur * B_STAGE_W;

        #pragma unroll
        for (int ks = 0; ks < 2; ks++) {
            const int k8 = ks * 8;
            uint32_t bh[8][2], bl[8][2];
            #pragma unroll
            for (int nt = 0; nt < 8; nt++) {
                const int n = nW + nt * 8 + g;
                bh[nt][0] = Bhc[(k8 + tig)     * BS_W + n];
                bh[nt][1] = Bhc[(k8 + tig + 4) * BS_W + n];
                if (SPLIT) {
                    bl[nt][0] = Blc[(k8 + tig)     * BS_W + n];
                    bl[nt][1] = Blc[(k8 + tig + 4) * BS_W + n];
                }
            }
            #pragma unroll
            for (int mt = 0; mt < 4; mt++) {
                const int r0 = mW + mt * 16 + g;
                uint32_t ah[4], al[4];
                ah[0] = Ahc[ r0      * AS_W + k8 + tig];
                ah[1] = Ahc[(r0 + 8) * AS_W + k8 + tig];
                ah[2] = Ahc[ r0      * AS_W + k8 + tig + 4];
                ah[3] = Ahc[(r0 + 8) * AS_W + k8 + tig + 4];
                if (SPLIT) {
                    al[0] = Alc[ r0      * AS_W + k8 + tig];
                    al[1] = Alc[(r0 + 8) * AS_W + k8 + tig];
                    al[2] = Alc[ r0      * AS_W + k8 + tig + 4];
                    al[3] = Alc[(r0 + 8) * AS_W + k8 + tig + 4];
                }
                #pragma unroll
                for (int nt = 0; nt < 8; nt++) {
                    mma_bf16(acc[mt][nt], ah, bh[nt]);
                    if (SPLIT) {
                        mma_bf16(acc[mt][nt], al, bh[nt]);
                        mma_bf16(acc[mt][nt], ah, bl[nt]);
                    }
                }
            }
        }
        __syncthreads();
    }

    // ---- epilogue --------------------------------------------------------
    if (MODE == 0) {
        // partial logits: p[token] += gelu(acc + b1) @ gw2  (over this block's
        // 128 channels). Deterministic: nt order, shfl tig order, nW0 then nW64.
        float4* w2s = (float4*)sm;          // [128] channel -> (w2 e0..e3)
        float4* lps = (float4*)sm + 128;    // [128] per-token partial
        w2s[tid] = *((const float4*)gw2 + (n0 + tid));
        __syncthreads();

        float4 p[8];
        #pragma unroll
        for (int r = 0; r < 8; r++) p[r] = make_float4(0.f, 0.f, 0.f, 0.f);

        #pragma unroll
        for (int nt = 0; nt < 8; nt++) {
            const int colL = nW + nt * 8 + tig * 2;
            float2 bv = *(const float2*)(bias + n0 + colL);
            float4 wA = w2s[colL];
            float4 wB = w2s[colL + 1];
            #pragma unroll
            for (int mt = 0; mt < 4; mt++)
                #pragma unroll
                for (int half = 0; half < 2; half++) {
                    const int r = mt * 2 + half;
                    float v0 = gelu_tanh(acc[mt][nt][half * 2 + 0] + bv.x);
                    float v1 = gelu_tanh(acc[mt][nt][half * 2 + 1] + bv.y);
                    p[r].x += v0 * wA.x + v1 * wB.x;
                    p[r].y += v0 * wA.y + v1 * wB.y;
                    p[r].z += v0 * wA.z + v1 * wB.z;
                    p[r].w += v0 * wA.w + v1 * wB.w;
                }
        }
        // reduce over tig (lane bits 0-1)
        #pragma unroll
        for (int r = 0; r < 8; r++) {
            #pragma unroll
            for (int o = 1; o <= 2; o <<= 1) {
                p[r].x += __shfl_xor_sync(0xffffffffu, p[r].x, o);
                p[r].y += __shfl_xor_sync(0xffffffffu, p[r].y, o);
                p[r].z += __shfl_xor_sync(0xffffffffu, p[r].z, o);
                p[r].w += __shfl_xor_sync(0xffffffffu, p[r].w, o);
            }
        }
        if (nW == 0 && tig == 0) {
            #pragma unroll
            for (int mt = 0; mt < 4; mt++)
                #pragma unroll
                for (int half = 0; half < 2; half++)
                    lps[mW + mt * 16 + g + half * 8] = p[mt * 2 + half];
        }
        __syncthreads();
        if (nW == 64 && tig == 0) {
            #pragma unroll
            for (int mt = 0; mt < 4; mt++)
                #pragma unroll
                for (int half = 0; half < 2; half++) {
                    const int r = mW + mt * 16 + g + half * 8;
                    float4 a = lps[r];
                    float4 b = p[mt * 2 + half];
                    lps[r] = make_float4(a.x + b.x, a.y + b.y, a.z + b.z, a.w + b.w);
                }
        }
        __syncthreads();
        g_lpart[(size_t)by * NTOK + m0 + tid] = lps[tid];
        return;
    }

    #pragma unroll
    for (int mt = 0; mt < 4; mt++) {
        #pragma unroll
        for (int half = 0; half < 2; half++) {
            const int m = m0 + mW + mt * 16 + g + half * 8;
            if (m >= cnt) continue;
            float gv = 1.f;
            if (MODE == 2) gv = g_gv[g_perm[base + m]];
            #pragma unroll
            for (int nt = 0; nt < 8; nt++) {
                const int col = n0 + nW + nt * 8 + tig * 2;
                float2 bv = *(const float2*)(bias + col);
                float v0 = acc[mt][nt][half * 2 + 0] + bv.x;
                float v1 = acc[mt][nt][half * 2 + 1] + bv.y;
                if (MODE == 1) {
                    __nv_bfloat162* hrow = (__nv_bfloat162*)(g_H + (size_t)(base + m) * C);
                    hrow[col >> 1] = __floats2bfloat162_rn(gelu_tanh(v0), gelu_tanh(v1));
                } else {
                    float* orow = g_X + (size_t)(base + m) * C;
                    *(float2*)(orow + col) = make_float2(v0 * gv, v1 * gv);
                }
            }
        }
    }
}

// ---------------------------------------------------------------------------
// 3. routing: combine logit partials + b2 -> softmax/top-1 -> counts/scan/perm
// Single block, 1024 threads (no cross-block sync needed).
// ---------------------------------------------------------------------------
__global__ void route_k(const float* __restrict__ b2) {
    __shared__ int cnts[NE], offs[NE], fill[NE];
    const int tid = threadIdx.x;
    const int lane = tid & 31;
    if (tid < NE) cnts[tid] = 0;
    __syncthreads();

    const float4 b2v = *(const float4*)b2;

    for (int n = tid; n < NTOK; n += 1024) {
        float4 l = b2v;
        #pragma unroll
        for (int pp = 0; pp < NT; pp++) {
            float4 q = g_lpart[(size_t)pp * NTOK + n];
            l.x += q.x; l.y += q.y; l.z += q.z; l.w += q.w;
        }
        float m = l.x; int idx = 0;
        if (l.y > m) { m = l.y; idx = 1; }   // strict '>' = jnp.argmax first-max
        if (l.z > m) { m = l.z; idx = 2; }
        if (l.w > m) { m = l.w; idx = 3; }
        float s = expf(l.x - m) + expf(l.y - m) + expf(l.z - m) + expf(l.w - m);
        g_top[n] = idx;
        g_gv[n]  = 1.0f / s;
        // warp-aggregated histogram
        #pragma unroll
        for (int ee = 0; ee < NE; ee++) {
            unsigned msk = __ballot_sync(0xffffffffu, idx == ee);
            if (lane == 0 && msk) atomicAdd(&cnts[ee], __popc(msk));
        }
    }
    __syncthreads();
    if (tid == 0) {
        int s = 0;
        #pragma unroll
        for (int ee = 0; ee < NE; ee++) {
            offs[ee] = s; g_offsets[ee] = s;
            s += cnts[ee];
            fill[ee] = 0;
        }
        g_offsets[NE] = s;
    }
    __syncthreads();
    for (int n = tid; n < NTOK; n += 1024) {
        int e = g_top[n];
        int pos = 0;
        #pragma unroll
        for (int ee = 0; ee < NE; ee++) {
            unsigned msk = __ballot_sync(0xffffffffu, e == ee);
            if (e == ee) {
                int leader = __ffs(msk) - 1;
                int bse = 0;
                if (lane == leader) bse = atomicAdd(&fill[ee], __popc(msk));
                bse = __shfl_sync(msk, bse, leader);
                pos = bse + __popc(msk & ((1u << lane) - 1u));
            }
        }
        int gg = offs[e] + pos;
        g_perm[gg]  = n;
        g_tok2g[n]  = gg;
    }
}

// ---------------------------------------------------------------------------
// 8. coalesced scatter back to BCHW + residual
// ---------------------------------------------------------------------------
__global__ void scatter_k(const float* __restrict__ s32, float* __restrict__ out32) {
    __shared__ float tile[32][33];
    int b = blockIdx.z, c0 = blockIdx.y * 32, hw0 = blockIdx.x * 32;
    int tx = threadIdx.x, ty = threadIdx.y;   // (32, 8)
    for (int t = ty; t < 32; t += 8) {
        int n = b * 1024 + hw0 + t;
        int gg = g_tok2g[n];
        tile[t][tx] = g_X[(size_t)gg * C + c0 + tx];
    }
    __syncthreads();
    int ibase = b * (C * 1024) + hw0;
    #pragma unroll
    for (int j = 0; j < 4; j++) {
        int c = c0 + ty + 8 * j;
        int idx = ibase + c * 1024 + tx;
        out32[idx] = tile[tx][ty + 8 * j] + s32[idx];
    }
}

// ---------------------------------------------------------------------------
// launch
// ---------------------------------------------------------------------------
extern "C" void kernel_launch(void* const* d_in, const int* in_sizes, int n_in,
                              void* d_out, int out_size) {
    const float* s4  = (const float*)d_in[0];
    const float* s8  = (const float*)d_in[1];
    const float* s16 = (const float*)d_in[2];
    const float* s32 = (const float*)d_in[3];
    const float* gw1 = (const float*)d_in[4];
    const float* gb1 = (const float*)d_in[5];
    const float* gw2 = (const float*)d_in[6];
    const float* gb2 = (const float*)d_in[7];
    const float* ew1 = (const float*)d_in[8];
    const float* eb1 = (const float*)d_in[9];
    const float* ew2 = (const float*)d_in[10];
    const float* eb2 = (const float*)d_in[11];
    float* out = (float*)d_out;

    cudaFuncSetAttribute(mma_gemm_k<0>, cudaFuncAttributeMaxDynamicSharedMemorySize, SMEM_SPLIT_BYTES);

    // prep: transpose s32 -> hi/lo bf16 tokens, split/pack gate w1
    prep_k<<<6144 + 256, dim3(32, 8)>>>(s32, gw1);

    // gate hidden + fused logit partials (split-bf16) + s4 copy + expert weight convert
    mma_gemm_k<0><<<NB_COPY + NB_CONV + MT * NT, 128, SMEM_SPLIT_BYTES>>>(
        gb1, gw2, (const float4*)s4, (float4*)out, S4_ELEMS / 4, ew1, ew2, NB_COPY + NB_CONV);

    // routing: combine partials, softmax/top-1, counts, scan, perm (one block)
    route_k<<<1, 1024>>>(gb2);

    // expert up (bf16) + s8 copy
    mma_gemm_k<1><<<NB_COPY + MT * NT * NE, 128, SMEM_PLAIN_BYTES>>>(
        eb1, nullptr, (const float4*)s8, (float4*)(out + OFF_S8), S8_ELEMS / 4,
        nullptr, nullptr, NB_COPY);

    // expert down (bf16) + s16 copy
    mma_gemm_k<2><<<NB_COPY + MT * NT * NE, 128, SMEM_PLAIN_BYTES>>>(
        eb2, nullptr, (const float4*)s16, (float4*)(out + OFF_S16), S16_ELEMS / 4,
        nullptr, nullptr, NB_COPY);

    // scatter + residual into out32
    scatter_k<<<dim3(32, 24, 8), dim3(32, 8)>>>(s32, out + OFF_S32);
}

// round 9
// speedup vs baseline: 1.0115x; 1.0115x over previous
#include <cuda_runtime.h>
#include <cuda_bf16.h>
#include <math.h>
#include <stdint.h>

// ---------------------------------------------------------------------------
// Problem constants
// ---------------------------------------------------------------------------
#define NTOK 8192           // 8 * 32 * 32 tokens at stride 32
#define C    768            // channels
#define K2C  384            // C/2 (k-pair rows of packed weights)
#define NE   4              // experts

#define S4_ELEMS  50331648  // 8*96*256*256
#define S8_ELEMS  25165824  // 8*192*128*128
#define S16_ELEMS 12582912  // 8*384*64*64
#define OFF_S8   50331648
#define OFF_S16  75497472
#define OFF_S32  88080384

// GEMM tiling (bf16 m16n8k16, block 128x128, 8 warps of 64x32, 256 threads)
#define TBM 128
#define TBN 128
#define TBK 32              // k per smem stage (2 x k16 mma steps)
#define AS_W 20             // u32 words per A smem row (32 bf16 data + pad)
#define BS_W 136            // u32 words per B smem row (128 data + 8 pad)
#define A_STAGE_W (TBM * AS_W)        // 2560 words
#define B_STAGE_W ((TBK/2) * BS_W)    // 2176 words
#define SMEM_PLAIN_BYTES ((2*A_STAGE_W + 2*B_STAGE_W) * 4)          // 37888
#define SMEM_SPLIT_BYTES ((4*A_STAGE_W + 4*B_STAGE_W) * 4)          // 75776

#define MT (NTOK / TBM)     // 64 m-tiles
#define NT (C / TBN)        // 6  n-tiles
#define NB_COPY 148         // copy blocks PREPENDED per GEMM launch
#define NB_CONV 256         // expert-weight convert blocks (gate launch only)

// ---------------------------------------------------------------------------
// Scratch (device globals: no allocation allowed)
// ---------------------------------------------------------------------------
__device__ __nv_bfloat16 g_Xb[NTOK * C];   // tokens hi bf16
__device__ __nv_bfloat16 g_Xl[NTOK * C];   // tokens lo bf16 (split residual)
__device__ __nv_bfloat16 g_H [NTOK * C];   // expert hidden (compact, bf16)
__device__ float g_X [NTOK * C];           // Y (expert output, fp32, compact)
__device__ float4 g_lpart[NT * NTOK];      // per-n-block partial logits
__device__ uint32_t g_gw1h[K2C * C];       // gate w1 hi, k-pair packed bf16x2
__device__ uint32_t g_gw1l[K2C * C];       // gate w1 lo
__device__ uint32_t g_ew1b[NE * K2C * C];  // expert w1 bf16 packed
__device__ uint32_t g_ew2b[NE * K2C * C];  // expert w2 bf16 packed
__device__ int   g_top[NTOK];
__device__ float g_gv[NTOK];
__device__ int   g_perm[NTOK];
__device__ int   g_tok2g[NTOK];
__device__ int   g_offsets[NE + 1];

// ---------------------------------------------------------------------------
// Helpers
// ---------------------------------------------------------------------------
__device__ __forceinline__ float gelu_tanh(float x) {
    float x3 = x * x * x;
    return 0.5f * x * (1.0f + tanhf(0.7978845608028654f * x + 0.035677408136300125f * x3));
}

__device__ __forceinline__ void cp_async16(uint32_t smem_dst, const void* gsrc, bool valid) {
    int sz = valid ? 16 : 0;
    asm volatile("cp.async.cg.shared.global [%0], [%1], 16, %2;\n"
                 :: "r"(smem_dst), "l"(gsrc), "r"(sz));
}
__device__ __forceinline__ void cp_commit() { asm volatile("cp.async.commit_group;\n"); }
__device__ __forceinline__ void cp_wait0()  { asm volatile("cp.async.wait_group 0;\n"); }

__device__ __forceinline__ void mma_bf16(float* c, const uint32_t* a, const uint32_t* b) {
    asm volatile(
        "mma.sync.aligned.m16n8k16.row.col.f32.bf16.bf16.f32 "
        "{%0,%1,%2,%3},{%4,%5,%6,%7},{%8,%9},{%0,%1,%2,%3};\n"
        : "+f"(c[0]), "+f"(c[1]), "+f"(c[2]), "+f"(c[3])
        : "r"(a[0]), "r"(a[1]), "r"(a[2]), "r"(a[3]), "r"(b[0]), "r"(b[1]));
}

__device__ __forceinline__ uint32_t pack_bf16x2(float v0, float v1) {
    uint32_t r;
    asm("cvt.rn.bf16x2.f32 %0, %1, %2;" : "=r"(r) : "f"(v1), "f"(v0));
    return r;
}

// grid-stride copy, 4 float4 / thread / 1024-float4 window (cnt4 % 1024 == 0)
__device__ __forceinline__ void do_copy(int blk, int tid,
                                        const float4* __restrict__ s,
                                        float4* __restrict__ d, int cnt4) {
    size_t i = (size_t)blk * 1024 + tid;
    const size_t stride = (size_t)NB_COPY * 1024;
    for (; i < (size_t)cnt4; i += stride) {
        float4 v0 = s[i];
        float4 v1 = s[i + 256];
        float4 v2 = s[i + 512];
        float4 v3 = s[i + 768];
        d[i]       = v0;
        d[i + 256] = v1;
        d[i + 512] = v2;
        d[i + 768] = v3;
    }
}

// ---------------------------------------------------------------------------
// 1. prep launch: BCHW->token transpose (hi/lo bf16) + gate-w1 split/pack
// ---------------------------------------------------------------------------
__global__ void prep_k(const float* __restrict__ s32, const float* __restrict__ gw1) {
    int blk = blockIdx.x;
    int tx = threadIdx.x, ty = threadIdx.y;   // (32, 8)

    if (blk < 6144) {
        __shared__ float tile[32][33];
        int bx = blk & 31;
        int t  = blk >> 5;
        int by = t % 24;
        int bz = t / 24;
        int c0 = by * 32, hw0 = bx * 32;
        const float* src = s32 + ((size_t)bz * C + c0) * 1024 + hw0;
        #pragma unroll
        for (int j = 0; j < 32; j += 8)
            tile[ty + j][tx] = src[(ty + j) * 1024 + tx];
        __syncthreads();
        size_t dbase = ((size_t)(bz * 1024 + hw0)) * C + c0;
        #pragma unroll
        for (int j = 0; j < 32; j += 8) {
            float x = tile[tx][ty + j];
            __nv_bfloat16 h = __float2bfloat16(x);
            float r = x - __bfloat162float(h);
            size_t idx = dbase + (size_t)(ty + j) * C + tx;
            g_Xb[idx] = h;
            g_Xl[idx] = __float2bfloat16(r);
        }
    } else {
        int tid = ty * 32 + tx;
        const int total = K2C * C;
        for (int w = (blk - 6144) * 256 + tid; w < total; w += 256 * 256) {
            int k2 = w / C, n = w - k2 * C;
            float w0 = gw1[(size_t)(2 * k2) * C + n];
            float w1 = gw1[(size_t)(2 * k2 + 1) * C + n];
            float h0 = __bfloat162float(__float2bfloat16(w0));
            float h1 = __bfloat162float(__float2bfloat16(w1));
            g_gw1h[w] = pack_bf16x2(h0, h1);
            g_gw1l[w] = pack_bf16x2(w0 - h0, w1 - h1);
        }
    }
}

// ---------------------------------------------------------------------------
// bf16 GEMM: block 128x128, 8 warps (2m x 4n) of 64x32, 256 threads.
//   MODE 0 (split-bf16): hidden = gelu(X@gw1+b1); epilogue reduces partial
//                        logits (hidden @ gw2) into g_lpart. No hidden store.
//   MODE 1 (plain bf16): H = gelu(gather(Xb)@ew1+b1) -> g_H (bf16)
//   MODE 2 (plain bf16): Y = (H@ew2+b2)*gate_val     -> g_X (fp32)
// Copy blocks first; MODE 0 also hosts expert-weight convert blocks.
// ---------------------------------------------------------------------------
template <int MODE>
__launch_bounds__(256)
__global__ void mma_gemm_k(const float* __restrict__ Ball,
                           const float* __restrict__ gw2,
                           const float4* __restrict__ csrc, float4* __restrict__ cdst, int cnt4,
                           const float* __restrict__ cvt1, const float* __restrict__ cvt2,
                           int nbPre) {
    constexpr bool SPLIT = (MODE == 0);
    const int blk = blockIdx.x;
    const int tid = threadIdx.x;

    // ---- copy role -------------------------------------------------------
    if (blk < NB_COPY) { do_copy(blk, tid, csrc, cdst, cnt4); return; }

    // ---- expert weight convert role (gate launch only) -------------------
    if (MODE == 0 && blk < nbPre) {
        const int cb = blk - NB_COPY;
        const int WCNT = NE * K2C * C;
        for (int w = cb * 256 + tid; w < 2 * WCNT; w += NB_CONV * 256) {
            int wi = w;
            const float* src; uint32_t* dst;
            if (wi < WCNT) { src = cvt1; dst = g_ew1b; }
            else           { wi -= WCNT; src = cvt2; dst = g_ew2b; }
            int k2g = wi / C, n = wi - k2g * C;
            float w0 = src[(size_t)(2 * k2g) * C + n];
            float w1 = src[(size_t)(2 * k2g + 1) * C + n];
            dst[wi] = pack_bf16x2(w0, w1);
        }
        return;
    }

    // ---- GEMM role -------------------------------------------------------
    const int gblk = blk - nbPre;
    int e, bx, by;
    if (MODE == 0) { e = 0; bx = gblk & (MT - 1); by = gblk >> 6; }
    else { e = gblk / (MT * NT); int r = gblk - e * (MT * NT); bx = r & (MT - 1); by = r >> 6; }

    int base, cnt;
    if (MODE == 0) { base = 0; cnt = NTOK; }
    else           { base = g_offsets[e]; cnt = g_offsets[e + 1] - base; }

    const int m0 = bx * TBM;
    if (m0 >= cnt) return;
    const int n0 = by * TBN;

    const uint32_t* Wh = (MODE == 0) ? g_gw1h
                        : (MODE == 1) ? (g_ew1b + (size_t)e * K2C * C)
                                      : (g_ew2b + (size_t)e * K2C * C);
    const uint32_t* Wl = g_gw1l;   // only used when SPLIT
    const float* bias  = Ball + ((MODE == 0) ? 0 : e * C);

    extern __shared__ uint32_t sm[];
    uint32_t* AhB = sm;
    uint32_t* AlB = sm + 2 * A_STAGE_W;
    uint32_t* BhB = sm + (SPLIT ? 4 : 2) * A_STAGE_W;
    uint32_t* BlB = BhB + 2 * B_STAGE_W;
    const uint32_t sAh = (uint32_t)__cvta_generic_to_shared(AhB);
    const uint32_t sAl = (uint32_t)__cvta_generic_to_shared(AlB);
    const uint32_t sBh = (uint32_t)__cvta_generic_to_shared(BhB);
    const uint32_t sBl = (uint32_t)__cvta_generic_to_shared(BlB);

    const int wid  = tid >> 5;
    const int lane = tid & 31;
    const int g    = lane >> 2;
    const int tig  = lane & 3;
    const int mW   = (wid & 1) * 64;     // m 0-63 or 64-127
    const int nW   = (wid >> 1) * 32;    // n slice of 32 per warp pair-group

    // A loader: 2 x 16B chunks / thread / stage (per array)
    const __nv_bfloat16* Asrc = (MODE == 2) ? g_H : g_Xb;
    const uint8_t* srcA[2]; const uint8_t* srcAL[2]; uint32_t dstA[2]; bool vA[2];
    #pragma unroll
    for (int i = 0; i < 2; i++) {
        int q = tid + i * 256;
        int chunk = q >> 7;          // 0..3
        int row   = q & 127;
        int m = m0 + row;
        bool v = (m < cnt);
        int ar = 0;
        if (v) {
            if      (MODE == 1) ar = g_perm[base + m];
            else if (MODE == 2) ar = base + m;
            else                ar = m;
        }
        size_t boff = (size_t)ar * C * 2 + chunk * 16;
        srcA[i]  = (const uint8_t*)Asrc + boff;
        srcAL[i] = (const uint8_t*)g_Xl + boff;
        dstA[i]  = (uint32_t)(row * AS_W + chunk * 4) * 4u;
        vA[i] = v;
    }
    // B loader: 2 x 16B chunks / thread / stage
    size_t srcBoff[2]; uint32_t dstB[2];
    #pragma unroll
    for (int i = 0; i < 2; i++) {
        int q = tid + i * 256;
        int k2r = q >> 5;            // 0..15
        int c   = q & 31;            // 0..31
        srcBoff[i] = (size_t)k2r * C + n0 + c * 4;
        dstB[i]    = (uint32_t)(k2r * BS_W + c * 4) * 4u;
    }

    float acc[4][4][4];
    #pragma unroll
    for (int mt = 0; mt < 4; mt++)
        #pragma unroll
        for (int nt = 0; nt < 4; nt++)
            #pragma unroll
            for (int r = 0; r < 4; r++) acc[mt][nt][r] = 0.f;

    const int T = C / TBK;  // 24

    // prologue: stage 0
    #pragma unroll
    for (int i = 0; i < 2; i++) cp_async16(sAh + dstA[i], srcA[i], vA[i]);
    if (SPLIT)
        #pragma unroll
        for (int i = 0; i < 2; i++) cp_async16(sAl + dstA[i], srcAL[i], vA[i]);
    #pragma unroll
    for (int i = 0; i < 2; i++) cp_async16(sBh + dstB[i], Wh + srcBoff[i], true);
    if (SPLIT)
        #pragma unroll
        for (int i = 0; i < 2; i++) cp_async16(sBl + dstB[i], Wl + srcBoff[i], true);
    cp_commit();

    for (int t = 0; t < T; t++) {
        const int cur = t & 1;
        cp_wait0();
        __syncthreads();

        if (t + 1 < T) {
            const int nxt = cur ^ 1;
            const int kb = (t + 1) * (TBK * 2);                 // bytes into A rows
            const size_t kw = (size_t)(t + 1) * (TBK / 2) * C;  // words into W
            #pragma unroll
            for (int i = 0; i < 2; i++)
                cp_async16(sAh + nxt * (A_STAGE_W * 4) + dstA[i], srcA[i] + kb, vA[i]);
            if (SPLIT)
                #pragma unroll
                for (int i = 0; i < 2; i++)
                    cp_async16(sAl + nxt * (A_STAGE_W * 4) + dstA[i], srcAL[i] + kb, vA[i]);
            #pragma unroll
            for (int i = 0; i < 2; i++)
                cp_async16(sBh + nxt * (B_STAGE_W * 4) + dstB[i], Wh + srcBoff[i] + kw, true);
            if (SPLIT)
                #pragma unroll
                for (int i = 0; i < 2; i++)
                    cp_async16(sBl + nxt * (B_STAGE_W * 4) + dstB[i], Wl + srcBoff[i] + kw, true);
            cp_commit();
        }

        const uint32_t* Ahc = AhB + cur * A_STAGE_W;
        const uint32_t* Alc = AlB + cur * A_STAGE_W;
        const uint32_t* Bhc = BhB + cur * B_STAGE_W;
        const uint32_t* Blc = BlB + cur * B_STAGE_W;

        #pragma unroll
        for (int ks = 0; ks < 2; ks++) {
            const int k8 = ks * 8;
            uint32_t bh[4][2], bl[4][2];
            #pragma unroll
            for (int nt = 0; nt < 4; nt++) {
                const int n = nW + nt * 8 + g;
                bh[nt][0] = Bhc[(k8 + tig)     * BS_W + n];
                bh[nt][1] = Bhc[(k8 + tig + 4) * BS_W + n];
                if (SPLIT) {
                    bl[nt][0] = Blc[(k8 + tig)     * BS_W + n];
                    bl[nt][1] = Blc[(k8 + tig + 4) * BS_W + n];
                }
            }
            #pragma unroll
            for (int mt = 0; mt < 4; mt++) {
                const int r0 = mW + mt * 16 + g;
                uint32_t ah[4], al[4];
                ah[0] = Ahc[ r0      * AS_W + k8 + tig];
                ah[1] = Ahc[(r0 + 8) * AS_W + k8 + tig];
                ah[2] = Ahc[ r0      * AS_W + k8 + tig + 4];
                ah[3] = Ahc[(r0 + 8) * AS_W + k8 + tig + 4];
                if (SPLIT) {
                    al[0] = Alc[ r0      * AS_W + k8 + tig];
                    al[1] = Alc[(r0 + 8) * AS_W + k8 + tig];
                    al[2] = Alc[ r0      * AS_W + k8 + tig + 4];
                    al[3] = Alc[(r0 + 8) * AS_W + k8 + tig + 4];
                }
                #pragma unroll
                for (int nt = 0; nt < 4; nt++) {
                    mma_bf16(acc[mt][nt], ah, bh[nt]);
                    if (SPLIT) {
                        mma_bf16(acc[mt][nt], al, bh[nt]);
                        mma_bf16(acc[mt][nt], ah, bl[nt]);
                    }
                }
            }
        }
        __syncthreads();
    }

    // ---- epilogue --------------------------------------------------------
    if (MODE == 0) {
        // partial logits: p[token] += gelu(acc + b1) @ gw2 over this block's
        // 128 channels. Deterministic everywhere: fixed nt order, fixed shfl
        // order, fixed 4-way n-warp combine order via smem stage.
        float4* w2s     = (float4*)sm;          // [128] channel -> (w2 e0..e3)
        float4* lpstage = (float4*)sm + 128;    // [4][128] per-(n-warp-group, token)
        if (tid < 128) w2s[tid] = *((const float4*)gw2 + (n0 + tid));
        __syncthreads();

        float4 p[8];
        #pragma unroll
        for (int r = 0; r < 8; r++) p[r] = make_float4(0.f, 0.f, 0.f, 0.f);

        #pragma unroll
        for (int nt = 0; nt < 4; nt++) {
            const int colL = nW + nt * 8 + tig * 2;
            float2 bv = *(const float2*)(bias + n0 + colL);
            float4 wA = w2s[colL];
            float4 wB = w2s[colL + 1];
            #pragma unroll
            for (int mt = 0; mt < 4; mt++)
                #pragma unroll
                for (int half = 0; half < 2; half++) {
                    const int r = mt * 2 + half;
                    float v0 = gelu_tanh(acc[mt][nt][half * 2 + 0] + bv.x);
                    float v1 = gelu_tanh(acc[mt][nt][half * 2 + 1] + bv.y);
                    p[r].x += v0 * wA.x + v1 * wB.x;
                    p[r].y += v0 * wA.y + v1 * wB.y;
                    p[r].z += v0 * wA.z + v1 * wB.z;
                    p[r].w += v0 * wA.w + v1 * wB.w;
                }
        }
        // reduce over tig (lane bits 0-1)
        #pragma unroll
        for (int r = 0; r < 8; r++) {
            #pragma unroll
            for (int o = 1; o <= 2; o <<= 1) {
                p[r].x += __shfl_xor_sync(0xffffffffu, p[r].x, o);
                p[r].y += __shfl_xor_sync(0xffffffffu, p[r].y, o);
                p[r].z += __shfl_xor_sync(0xffffffffu, p[r].z, o);
                p[r].w += __shfl_xor_sync(0xffffffffu, p[r].w, o);
            }
        }
        // stage per n-warp-group partials (two m-warps fill all 128 rows)
        if (tig == 0) {
            const int nwarp = wid >> 1;
            #pragma unroll
            for (int mt = 0; mt < 4; mt++)
                #pragma unroll
                for (int half = 0; half < 2; half++)
                    lpstage[nwarp * 128 + mW + mt * 16 + g + half * 8] = p[mt * 2 + half];
        }
        __syncthreads();
        // fixed-order combine across the 4 n-warp groups
        if (tid < 128) {
            float4 s0 = lpstage[tid];
            float4 s1 = lpstage[128 + tid];
            float4 s2 = lpstage[256 + tid];
            float4 s3 = lpstage[384 + tid];
            float4 r;
            r.x = ((s0.x + s1.x) + s2.x) + s3.x;
            r.y = ((s0.y + s1.y) + s2.y) + s3.y;
            r.z = ((s0.z + s1.z) + s2.z) + s3.z;
            r.w = ((s0.w + s1.w) + s2.w) + s3.w;
            g_lpart[(size_t)by * NTOK + m0 + tid] = r;
        }
        return;
    }

    #pragma unroll
    for (int mt = 0; mt < 4; mt++) {
        #pragma unroll
        for (int half = 0; half < 2; half++) {
            const int m = m0 + mW + mt * 16 + g + half * 8;
            if (m >= cnt) continue;
            float gv = 1.f;
            if (MODE == 2) gv = g_gv[g_perm[base + m]];
            #pragma unroll
            for (int nt = 0; nt < 4; nt++) {
                const int col = n0 + nW + nt * 8 + tig * 2;
                float2 bv = *(const float2*)(bias + col);
                float v0 = acc[mt][nt][half * 2 + 0] + bv.x;
                float v1 = acc[mt][nt][half * 2 + 1] + bv.y;
                if (MODE == 1) {
                    __nv_bfloat162* hrow = (__nv_bfloat162*)(g_H + (size_t)(base + m) * C);
                    hrow[col >> 1] = __floats2bfloat162_rn(gelu_tanh(v0), gelu_tanh(v1));
                } else {
                    float* orow = g_X + (size_t)(base + m) * C;
                    *(float2*)(orow + col) = make_float2(v0 * gv, v1 * gv);
                }
            }
        }
    }
}

// ---------------------------------------------------------------------------
// 3. routing: combine logit partials + b2 -> softmax/top-1 -> counts/scan/perm
// Single block, 1024 threads.
// ---------------------------------------------------------------------------
__global__ void route_k(const float* __restrict__ b2) {
    __shared__ int cnts[NE], offs[NE], fill[NE];
    const int tid = threadIdx.x;
    const int lane = tid & 31;
    if (tid < NE) cnts[tid] = 0;
    __syncthreads();

    const float4 b2v = *(const float4*)b2;

    for (int n = tid; n < NTOK; n += 1024) {
        float4 l = b2v;
        #pragma unroll
        for (int pp = 0; pp < NT; pp++) {
            float4 q = g_lpart[(size_t)pp * NTOK + n];
            l.x += q.x; l.y += q.y; l.z += q.z; l.w += q.w;
        }
        float m = l.x; int idx = 0;
        if (l.y > m) { m = l.y; idx = 1; }   // strict '>' = jnp.argmax first-max
        if (l.z > m) { m = l.z; idx = 2; }
        if (l.w > m) { m = l.w; idx = 3; }
        float s = expf(l.x - m) + expf(l.y - m) + expf(l.z - m) + expf(l.w - m);
        g_top[n] = idx;
        g_gv[n]  = 1.0f / s;
        #pragma unroll
        for (int ee = 0; ee < NE; ee++) {
            unsigned msk = __ballot_sync(0xffffffffu, idx == ee);
            if (lane == 0 && msk) atomicAdd(&cnts[ee], __popc(msk));
        }
    }
    __syncthreads();
    if (tid == 0) {
        int s = 0;
        #pragma unroll
        for (int ee = 0; ee < NE; ee++) {
            offs[ee] = s; g_offsets[ee] = s;
            s += cnts[ee];
            fill[ee] = 0;
        }
        g_offsets[NE] = s;
    }
    __syncthreads();
    for (int n = tid; n < NTOK; n += 1024) {
        int e = g_top[n];
        int pos = 0;
        #pragma unroll
        for (int ee = 0; ee < NE; ee++) {
            unsigned msk = __ballot_sync(0xffffffffu, e == ee);
            if (e == ee) {
                int leader = __ffs(msk) - 1;
                int bse = 0;
                if (lane == leader) bse = atomicAdd(&fill[ee], __popc(msk));
                bse = __shfl_sync(msk, bse, leader);
                pos = bse + __popc(msk & ((1u << lane) - 1u));
            }
        }
        int gg = offs[e] + pos;
        g_perm[gg]  = n;
        g_tok2g[n]  = gg;
    }
}

// ---------------------------------------------------------------------------
// 8. coalesced scatter back to BCHW + residual
// ---------------------------------------------------------------------------
__global__ void scatter_k(const float* __restrict__ s32, float* __restrict__ out32) {
    __shared__ float tile[32][33];
    int b = blockIdx.z, c0 = blockIdx.y * 32, hw0 = blockIdx.x * 32;
    int tx = threadIdx.x, ty = threadIdx.y;   // (32, 8)
    for (int t = ty; t < 32; t += 8) {
        int n = b * 1024 + hw0 + t;
        int gg = g_tok2g[n];
        tile[t][tx] = g_X[(size_t)gg * C + c0 + tx];
    }
    __syncthreads();
    int ibase = b * (C * 1024) + hw0;
    #pragma unroll
    for (int j = 0; j < 4; j++) {
        int c = c0 + ty + 8 * j;
        int idx = ibase + c * 1024 + tx;
        out32[idx] = tile[tx][ty + 8 * j] + s32[idx];
    }
}

// ---------------------------------------------------------------------------
// launch
// ---------------------------------------------------------------------------
extern "C" void kernel_launch(void* const* d_in, const int* in_sizes, int n_in,
                              void* d_out, int out_size) {
    const float* s4  = (const float*)d_in[0];
    const float* s8  = (const float*)d_in[1];
    const float* s16 = (const float*)d_in[2];
    const float* s32 = (const float*)d_in[3];
    const float* gw1 = (const float*)d_in[4];
    const float* gb1 = (const float*)d_in[5];
    const float* gw2 = (const float*)d_in[6];
    const float* gb2 = (const float*)d_in[7];
    const float* ew1 = (const float*)d_in[8];
    const float* eb1 = (const float*)d_in[9];
    const float* ew2 = (const float*)d_in[10];
    const float* eb2 = (const float*)d_in[11];
    float* out = (float*)d_out;

    cudaFuncSetAttribute(mma_gemm_k<0>, cudaFuncAttributeMaxDynamicSharedMemorySize, SMEM_SPLIT_BYTES);

    // prep: transpose s32 -> hi/lo bf16 tokens, split/pack gate w1
    prep_k<<<6144 + 256, dim3(32, 8)>>>(s32, gw1);

    // gate hidden + fused logit partials (split-bf16) + s4 copy + expert weight convert
    mma_gemm_k<0><<<NB_COPY + NB_CONV + MT * NT, 256, SMEM_SPLIT_BYTES>>>(
        gb1, gw2, (const float4*)s4, (float4*)out, S4_ELEMS / 4, ew1, ew2, NB_COPY + NB_CONV);

    // routing: combine partials, softmax/top-1, counts, scan, perm (one block)
    route_k<<<1, 1024>>>(gb2);

    // expert up (bf16) + s8 copy
    mma_gemm_k<1><<<NB_COPY + MT * NT * NE, 256, SMEM_PLAIN_BYTES>>>(
        eb1, nullptr, (const float4*)s8, (float4*)(out + OFF_S8), S8_ELEMS / 4,
        nullptr, nullptr, NB_COPY);

    // expert down (bf16) + s16 copy
    mma_gemm_k<2><<<NB_COPY + MT * NT * NE, 256, SMEM_PLAIN_BYTES>>>(
        eb2, nullptr, (const float4*)s16, (float4*)(out + OFF_S16), S16_ELEMS / 4,
        nullptr, nullptr, NB_COPY);

    // scatter + residual into out32
    scatter_k<<<dim3(32, 24, 8), dim3(32, 8)>>>(s32, out + OFF_S32);
}